// round 7
// baseline (speedup 1.0000x reference)
#include <cuda_runtime.h>
#include <cuda_bf16.h>
#include <math.h>

#define NN 100000
#define NE 2000000
#define HD 64
#define NL 3

// ---------------- scratch (device globals; ~112 MB total) ----------------
__device__ float          g_h[NN * HD];       // node state           25.6 MB
__device__ __nv_bfloat16  g_PQ[NN * 256];     // per-node P/Q (bf16)  51.2 MB
__device__ float          g_agg[NN * HD];     // aggregated message   25.6 MB
__device__ float g_W1cat[NL * 64 * 256];      // repacked mlp_w1       0.2 MB
__device__ float g_W2cat[NL * 128 * 64];      // repacked mlp_w2       0.1 MB
__device__ int   g_edge[NE];                  // dst-CSR packed (et<<30)|src  8 MB
__device__ int   g_deg[2 * NN];
__device__ int   g_rowoff[NN + 1];
__device__ int   g_cursor[NN];

// ---------------- small utility kernels ----------------
__global__ void zero_deg_kernel() {
    int i = blockIdx.x * blockDim.x + threadIdx.x;
    if (i < 2 * NN) g_deg[i] = 0;
}

// Repack mlp_w1 (L,E,128,64) -> W1cat[l][k][c], c = e*128 + half*64 + j
// and mlp_w2 (L,E,64,64) -> W2cat[l][k=e*64+kk][j]
__global__ void pack_kernel(const float* __restrict__ w1, const float* __restrict__ w2) {
    int i = blockIdx.x * blockDim.x + threadIdx.x;
    const int n1 = NL * 64 * 256;
    if (i < n1) {
        int l = i / (64 * 256);
        int rem = i - l * 64 * 256;
        int k = rem >> 8;
        int c = rem & 255;
        int e = c >> 7;
        int half = (c >> 6) & 1;
        int j = c & 63;
        g_W1cat[i] = w1[(((l * 2 + e) * 128) + half * 64 + k) * 64 + j];
    } else {
        int i2 = i - n1;
        if (i2 < NL * 128 * 64) {
            int l = i2 / (128 * 64);
            int rem = i2 - l * 128 * 64;
            int k = rem >> 6;
            int j = rem & 63;
            int e = k >> 6;
            int kk = k & 63;
            g_W2cat[i2] = w2[((l * 2 + e) * 64 + kk) * 64 + j];
        }
    }
}

// input proj + layernorm + relu; warp per node
__global__ void input_proj_kernel(const float* __restrict__ x, const float* __restrict__ W,
                                  const float* __restrict__ b, const float* __restrict__ g,
                                  const float* __restrict__ be) {
    int warp = (blockIdx.x * blockDim.x + threadIdx.x) >> 5;
    int lane = threadIdx.x & 31;
    if (warp >= NN) return;
    float x0 = x[warp * 4 + 0], x1 = x[warp * 4 + 1];
    float x2 = x[warp * 4 + 2], x3 = x[warp * 4 + 3];
    int j0 = lane, j1 = lane + 32;
    float y0 = b[j0] + x0 * W[j0] + x1 * W[64 + j0] + x2 * W[128 + j0] + x3 * W[192 + j0];
    float y1 = b[j1] + x0 * W[j1] + x1 * W[64 + j1] + x2 * W[128 + j1] + x3 * W[192 + j1];
    float s = y0 + y1;
    #pragma unroll
    for (int o = 16; o; o >>= 1) s += __shfl_xor_sync(0xffffffffu, s, o);
    float mu = s * (1.0f / 64.0f);
    float d0 = y0 - mu, d1 = y1 - mu;
    float v = d0 * d0 + d1 * d1;
    #pragma unroll
    for (int o = 16; o; o >>= 1) v += __shfl_xor_sync(0xffffffffu, v, o);
    float rs = rsqrtf(v * (1.0f / 64.0f) + 1e-5f);
    g_h[warp * 64 + j0] = fmaxf(d0 * rs * g[j0] + be[j0], 0.0f);
    g_h[warp * 64 + j1] = fmaxf(d1 * rs * g[j1] + be[j1], 0.0f);
}

__global__ void hist_kernel(const int* __restrict__ ei, const int* __restrict__ et) {
    int i = blockIdx.x * blockDim.x + threadIdx.x;
    if (i >= NE) return;
    int dst = ei[NE + i];
    atomicAdd(&g_deg[2 * dst + et[i]], 1);
}

// single-block exclusive scan of node degrees -> rowoff, cursor
__global__ void scan_kernel() {
    __shared__ int warp_sums[32];
    __shared__ int s_total;
    __shared__ int s_carry;
    int tid = threadIdx.x, lane = tid & 31, wid = tid >> 5;
    if (tid == 0) s_carry = 0;
    __syncthreads();
    for (int base = 0; base < NN; base += 1024) {
        int i = base + tid;
        int v = (i < NN) ? (g_deg[2 * i] + g_deg[2 * i + 1]) : 0;
        int incl = v;
        #pragma unroll
        for (int off = 1; off < 32; off <<= 1) {
            int t = __shfl_up_sync(0xffffffffu, incl, off);
            if (lane >= off) incl += t;
        }
        if (lane == 31) warp_sums[wid] = incl;
        __syncthreads();
        if (wid == 0) {
            int w = warp_sums[lane];
            int wi = w;
            #pragma unroll
            for (int off = 1; off < 32; off <<= 1) {
                int t = __shfl_up_sync(0xffffffffu, wi, off);
                if (lane >= off) wi += t;
            }
            warp_sums[lane] = wi - w;
            if (lane == 31) s_total = wi;
        }
        __syncthreads();
        int excl = incl - v + warp_sums[wid] + s_carry;
        if (i < NN) { g_rowoff[i] = excl; g_cursor[i] = excl; }
        __syncthreads();
        if (tid == 0) s_carry += s_total;
        __syncthreads();
    }
    if (threadIdx.x == 0) g_rowoff[NN] = s_carry;
}

__global__ void scatter_kernel(const int* __restrict__ ei, const int* __restrict__ et) {
    int i = blockIdx.x * blockDim.x + threadIdx.x;
    if (i >= NE) return;
    int dst = ei[NE + i];
    int src = ei[i];
    int pos = atomicAdd(&g_cursor[dst], 1);
    g_edge[pos] = src | (et[i] << 30);
}

// ---------------- PQ GEMM: PQ[N x 256] = h[N x 64] @ W1cat[64 x 256], bf16 out ----------------
// 64 rows/block, 256 threads; 64 col-threads x 4 cols, 4 row-threads x 16 rows.
__global__ __launch_bounds__(256) void pq_gemm_kernel(const float* __restrict__ A,
                                                      const float* __restrict__ B) {
    __shared__ float Ash[64 * 65];
    const int tid = threadIdx.x;
    const int row0 = blockIdx.x * 64;
    for (int i = tid; i < 64 * 64; i += 256) {
        int r = i >> 6, k = i & 63;
        int gr = row0 + r;
        Ash[k * 65 + r] = (gr < NN) ? A[gr * 64 + k] : 0.0f;
    }
    __syncthreads();
    const int colt = tid & 63;
    const int rowt = tid >> 6;
    const int c0 = colt * 4;
    const int r0 = rowt * 16;
    float acc[16][4];
    #pragma unroll
    for (int r = 0; r < 16; r++)
        #pragma unroll
        for (int c = 0; c < 4; c++) acc[r][c] = 0.0f;
    #pragma unroll 4
    for (int k = 0; k < 64; k++) {
        float4 b4 = *reinterpret_cast<const float4*>(&B[k * 256 + c0]);
        #pragma unroll
        for (int r = 0; r < 16; r++) {
            float a = Ash[k * 65 + r0 + r];
            acc[r][0] = fmaf(a, b4.x, acc[r][0]);
            acc[r][1] = fmaf(a, b4.y, acc[r][1]);
            acc[r][2] = fmaf(a, b4.z, acc[r][2]);
            acc[r][3] = fmaf(a, b4.w, acc[r][3]);
        }
    }
    #pragma unroll
    for (int r = 0; r < 16; r++) {
        int gr = row0 + r0 + r;
        if (gr < NN) {
            __nv_bfloat162 lo = __floats2bfloat162_rn(acc[r][0], acc[r][1]);
            __nv_bfloat162 hi = __floats2bfloat162_rn(acc[r][2], acc[r][3]);
            uint2 pk;
            pk.x = *reinterpret_cast<unsigned*>(&lo);
            pk.y = *reinterpret_cast<unsigned*>(&hi);
            *reinterpret_cast<uint2*>(&g_PQ[gr * 256 + c0]) = pk;
        }
    }
}

// ---------------- fused edge aggregation + W2 GEMV ----------------
// Warp per dst node; lane holds feature pair (2*lane, 2*lane+1) of each 64-wide row.
// One 128B bf16 gather per edge. Then agg = Hvec @ W2cat + deg0*b2[0:64] + deg1*b2[64:128].
__global__ __launch_bounds__(256) void agg_kernel(const float* __restrict__ b1,
                                                  const float* __restrict__ b2,
                                                  const float* __restrict__ W2) {
    __shared__ float sW2[128 * 64];
    __shared__ float sB2[128];
    int tid = threadIdx.x;
    for (int i = tid; i < 128 * 64; i += 256) sW2[i] = W2[i];
    if (tid < 128) sB2[tid] = b2[tid];
    __syncthreads();

    int node = blockIdx.x * 8 + (tid >> 5);
    int lane = tid & 31;
    if (node >= NN) return;
    const __nv_bfloat162* pq2 = reinterpret_cast<const __nv_bfloat162*>(g_PQ);
    // dst Q pairs: Q_e0 at feature offset 64, Q_e1 at 192 (in bf16 units)
    float2 q0 = __bfloat1622float2(pq2[node * 128 + 32 + lane]);
    float2 q1 = __bfloat1622float2(pq2[node * 128 + 96 + lane]);
    float b0x = b1[2 * lane], b0y = b1[2 * lane + 1];
    float b1x = b1[64 + 2 * lane], b1y = b1[64 + 2 * lane + 1];
    float a0x = 0.f, a0y = 0.f, a1x = 0.f, a1y = 0.f;
    int c0cnt = 0;
    int beg = g_rowoff[node], end = g_rowoff[node + 1];
    for (int i = beg; i < end; i++) {
        int p = g_edge[i];
        int src = p & 0x3FFFFFFF;
        int et = ((unsigned)p) >> 30;
        // P row of src for type et: bf16 offset src*256 + et*128 -> bf162 idx src*128 + et*64
        float2 v = __bfloat1622float2(__ldg(&pq2[src * 128 + et * 64 + lane]));
        if (et == 0) {
            a0x += fmaxf(v.x + q0.x + b0x, 0.f);
            a0y += fmaxf(v.y + q0.y + b0y, 0.f);
            c0cnt++;
        } else {
            a1x += fmaxf(v.x + q1.x + b1x, 0.f);
            a1y += fmaxf(v.y + q1.y + b1y, 0.f);
        }
    }
    float c1cnt = (float)((end - beg) - c0cnt);
    // GEMV: out[j] = sum_k Hvec[k]*W2[k][j]; lane t holds Hvec features 2t,2t+1 (e0) / 64+2t,+1 (e1)
    float o0 = (float)c0cnt * sB2[lane] + c1cnt * sB2[64 + lane];
    float o1 = (float)c0cnt * sB2[32 + lane] + c1cnt * sB2[96 + lane];
    #pragma unroll
    for (int t = 0; t < 32; t++) {
        float vx = __shfl_sync(0xffffffffu, a0x, t);
        float vy = __shfl_sync(0xffffffffu, a0y, t);
        o0 = fmaf(vx, sW2[(2 * t) * 64 + lane], o0);
        o0 = fmaf(vy, sW2[(2 * t + 1) * 64 + lane], o0);
        o1 = fmaf(vx, sW2[(2 * t) * 64 + 32 + lane], o1);
        o1 = fmaf(vy, sW2[(2 * t + 1) * 64 + 32 + lane], o1);
    }
    #pragma unroll
    for (int t = 0; t < 32; t++) {
        float vx = __shfl_sync(0xffffffffu, a1x, t);
        float vy = __shfl_sync(0xffffffffu, a1y, t);
        o0 = fmaf(vx, sW2[(64 + 2 * t) * 64 + lane], o0);
        o0 = fmaf(vy, sW2[(64 + 2 * t + 1) * 64 + lane], o0);
        o1 = fmaf(vx, sW2[(64 + 2 * t) * 64 + 32 + lane], o1);
        o1 = fmaf(vy, sW2[(64 + 2 * t + 1) * 64 + 32 + lane], o1);
    }
    g_agg[node * 64 + lane] = o0;
    g_agg[node * 64 + 32 + lane] = o1;
}

// ---------------- fused GRU: gi = agg@Wi, gh = h@Wh, gates, h update ----------------
__global__ __launch_bounds__(512) void gru_kernel(const float* __restrict__ Wi,
                                                  const float* __restrict__ Wh,
                                                  const float* __restrict__ bi,
                                                  const float* __restrict__ bh) {
    __shared__ float Aagg[64][65];
    __shared__ float Ahh[64][65];
    int tid = threadIdx.x;
    int row0 = blockIdx.x * 64;
    for (int i = tid; i < 64 * 64; i += 512) {
        int r = i >> 6, k = i & 63;
        int gr = row0 + r;
        float va = 0.f, vh = 0.f;
        if (gr < NN) { va = g_agg[gr * 64 + k]; vh = g_h[gr * 64 + k]; }
        Aagg[k][r] = va;
        Ahh[k][r] = vh;
    }
    __syncthreads();
    int j = tid & 63;
    int rowt = tid >> 6;  // 0..7
    float ai[8][3], ah[8][3];
    #pragma unroll
    for (int r = 0; r < 8; r++)
        #pragma unroll
        for (int c = 0; c < 3; c++) { ai[r][c] = 0.f; ah[r][c] = 0.f; }

    #pragma unroll 2
    for (int k = 0; k < 64; k++) {
        float wi0 = __ldg(&Wi[k * 192 + j]);
        float wi1 = __ldg(&Wi[k * 192 + 64 + j]);
        float wi2 = __ldg(&Wi[k * 192 + 128 + j]);
        float wh0 = __ldg(&Wh[k * 192 + j]);
        float wh1 = __ldg(&Wh[k * 192 + 64 + j]);
        float wh2 = __ldg(&Wh[k * 192 + 128 + j]);
        #pragma unroll
        for (int r = 0; r < 8; r++) {
            float a = Aagg[k][rowt * 8 + r];
            float hv = Ahh[k][rowt * 8 + r];
            ai[r][0] = fmaf(a, wi0, ai[r][0]);
            ai[r][1] = fmaf(a, wi1, ai[r][1]);
            ai[r][2] = fmaf(a, wi2, ai[r][2]);
            ah[r][0] = fmaf(hv, wh0, ah[r][0]);
            ah[r][1] = fmaf(hv, wh1, ah[r][1]);
            ah[r][2] = fmaf(hv, wh2, ah[r][2]);
        }
    }
    float bir = bi[j], biz = bi[64 + j], bin = bi[128 + j];
    float bhr = bh[j], bhz = bh[64 + j], bhn = bh[128 + j];
    #pragma unroll
    for (int r = 0; r < 8; r++) {
        int rl = rowt * 8 + r;
        int gr = row0 + rl;
        if (gr < NN) {
            float rg = 1.0f / (1.0f + expf(-((ai[r][0] + bir) + (ah[r][0] + bhr))));
            float zg = 1.0f / (1.0f + expf(-((ai[r][1] + biz) + (ah[r][1] + bhz))));
            float ng = tanhf((ai[r][2] + bin) + rg * (ah[r][2] + bhn));
            float hold = Ahh[j][rl];
            g_h[gr * 64 + j] = (1.0f - zg) * ng + zg * hold;
        }
    }
}

// ---------------- readout + final correction; warp per node ----------------
__global__ void readout_kernel(const float* __restrict__ w1, const float* __restrict__ b1,
                               const float* __restrict__ w2, const float* __restrict__ b2,
                               const int* __restrict__ ntype, const float* __restrict__ x,
                               float* __restrict__ out) {
    int node = (blockIdx.x * blockDim.x + threadIdx.x) >> 5;
    int lane = threadIdx.x & 31;
    if (node >= NN) return;
    float h0 = g_h[node * 64 + lane];
    float h1 = g_h[node * 64 + 32 + lane];
    float a0 = b1[lane], a1 = b1[32 + lane];
    #pragma unroll
    for (int k = 0; k < 32; k++) {
        float hk = __shfl_sync(0xffffffffu, h0, k);
        a0 = fmaf(hk, w1[k * 64 + lane], a0);
        a1 = fmaf(hk, w1[k * 64 + 32 + lane], a1);
    }
    #pragma unroll
    for (int k = 0; k < 32; k++) {
        float hk = __shfl_sync(0xffffffffu, h1, k);
        a0 = fmaf(hk, w1[(32 + k) * 64 + lane], a0);
        a1 = fmaf(hk, w1[(32 + k) * 64 + 32 + lane], a1);
    }
    a0 = fmaxf(a0, 0.0f);
    a1 = fmaxf(a1, 0.0f);
    float s = a0 * w2[lane] + a1 * w2[32 + lane];
    #pragma unroll
    for (int o = 16; o; o >>= 1) s += __shfl_xor_sync(0xffffffffu, s, o);
    if (lane == 0) {
        float o_ = s + b2[0];
        out[node] = (ntype[node] == 0) ? (x[node * 4] + o_) : 0.0f;
    }
}

// ---------------- launcher ----------------
extern "C" void kernel_launch(void* const* d_in, const int* in_sizes, int n_in,
                              void* d_out, int out_size) {
    const float* x          = (const float*)d_in[0];
    const int*   node_type  = (const int*)d_in[1];
    const int*   edge_index = (const int*)d_in[2];
    const int*   edge_type  = (const int*)d_in[3];
    const float* in_w       = (const float*)d_in[4];
    const float* in_b       = (const float*)d_in[5];
    const float* ln_g       = (const float*)d_in[6];
    const float* ln_b       = (const float*)d_in[7];
    const float* mlp_w1     = (const float*)d_in[8];
    const float* mlp_b1     = (const float*)d_in[9];
    const float* mlp_w2     = (const float*)d_in[10];
    const float* mlp_b2     = (const float*)d_in[11];
    const float* gru_wi     = (const float*)d_in[12];
    const float* gru_wh     = (const float*)d_in[13];
    const float* gru_bi     = (const float*)d_in[14];
    const float* gru_bh     = (const float*)d_in[15];
    const float* ro_w1      = (const float*)d_in[16];
    const float* ro_b1      = (const float*)d_in[17];
    const float* ro_w2      = (const float*)d_in[18];
    const float* ro_b2      = (const float*)d_in[19];
    float* out = (float*)d_out;

    float *p_h, *p_W1, *p_W2;
    cudaGetSymbolAddress((void**)&p_h, g_h);
    cudaGetSymbolAddress((void**)&p_W1, g_W1cat);
    cudaGetSymbolAddress((void**)&p_W2, g_W2cat);

    const int nwarp_blocks = (NN + 7) / 8;
    const int gemm_blocks  = (NN + 63) / 64;
    const int edge_blocks  = (NE + 255) / 256;

    zero_deg_kernel<<<(2 * NN + 255) / 256, 256>>>();
    pack_kernel<<<(NL * 64 * 256 + NL * 128 * 64 + 255) / 256, 256>>>(mlp_w1, mlp_w2);
    input_proj_kernel<<<nwarp_blocks, 256>>>(x, in_w, in_b, ln_g, ln_b);
    hist_kernel<<<edge_blocks, 256>>>(edge_index, edge_type);
    scan_kernel<<<1, 1024>>>();
    scatter_kernel<<<edge_blocks, 256>>>(edge_index, edge_type);

    for (int l = 0; l < NL; l++) {
        pq_gemm_kernel<<<gemm_blocks, 256>>>(p_h, p_W1 + l * 64 * 256);
        agg_kernel<<<nwarp_blocks, 256>>>(mlp_b1 + l * 2 * 64, mlp_b2 + l * 2 * 64,
                                          p_W2 + l * 128 * 64);
        gru_kernel<<<gemm_blocks, 512>>>(gru_wi + l * 64 * 192, gru_wh + l * 64 * 192,
                                         gru_bi + l * 192, gru_bh + l * 192);
    }

    readout_kernel<<<nwarp_blocks, 256>>>(ro_w1, ro_b1, ro_w2, ro_b2, node_type, x, out);
}

// round 9
// speedup vs baseline: 1.0711x; 1.0711x over previous
#include <cuda_runtime.h>
#include <cuda_bf16.h>
#include <math.h>

#define NN 100000
#define NE 2000000
#define HD 64
#define NL 3

typedef unsigned long long ull;

// packed f32x2 helpers (FFMA2 is only reachable via PTX)
__device__ __forceinline__ ull pack2(float x, float y) {
    ull r; asm("mov.b64 %0,{%1,%2};" : "=l"(r) : "f"(x), "f"(y)); return r;
}
__device__ __forceinline__ void unpack2(ull v, float& x, float& y) {
    asm("mov.b64 {%0,%1},%2;" : "=f"(x), "=f"(y) : "l"(v));
}
__device__ __forceinline__ void fma2(ull& d, ull a, ull b) {
    asm("fma.rn.f32x2 %0,%1,%2,%3;" : "=l"(d) : "l"(a), "l"(b), "l"(d));
}

// ---------------- scratch (device globals; ~112 MB total) ----------------
__device__ float          g_h[NN * HD];       // node state           25.6 MB
__device__ __nv_bfloat16  g_PQ[NN * 256];     // per-node P/Q (bf16)  51.2 MB
__device__ float          g_agg[NN * HD];     // aggregated message   25.6 MB
__device__ float g_W1cat[NL * 64 * 256];      // repacked mlp_w1       0.2 MB
__device__ float g_W2cat[NL * 128 * 64];      // repacked mlp_w2       0.1 MB
__device__ int   g_edge[NE];                  // dst-CSR packed (et<<30)|src  8 MB
__device__ int   g_deg[2 * NN];
__device__ int   g_rowoff[NN + 1];
__device__ int   g_cursor[NN];

// ---------------- small utility kernels ----------------
__global__ void zero_deg_kernel() {
    int i = blockIdx.x * blockDim.x + threadIdx.x;
    if (i < 2 * NN) g_deg[i] = 0;
}

// Repack mlp_w1 (L,E,128,64) -> W1cat[l][k][c], c = e*128 + half*64 + j
// and mlp_w2 (L,E,64,64) -> W2cat[l][k=e*64+kk][j]
__global__ void pack_kernel(const float* __restrict__ w1, const float* __restrict__ w2) {
    int i = blockIdx.x * blockDim.x + threadIdx.x;
    const int n1 = NL * 64 * 256;
    if (i < n1) {
        int l = i / (64 * 256);
        int rem = i - l * 64 * 256;
        int k = rem >> 8;
        int c = rem & 255;
        int e = c >> 7;
        int half = (c >> 6) & 1;
        int j = c & 63;
        g_W1cat[i] = w1[(((l * 2 + e) * 128) + half * 64 + k) * 64 + j];
    } else {
        int i2 = i - n1;
        if (i2 < NL * 128 * 64) {
            int l = i2 / (128 * 64);
            int rem = i2 - l * 128 * 64;
            int k = rem >> 6;
            int j = rem & 63;
            int e = k >> 6;
            int kk = k & 63;
            g_W2cat[i2] = w2[((l * 2 + e) * 64 + kk) * 64 + j];
        }
    }
}

// input proj + layernorm + relu; warp per node
__global__ void input_proj_kernel(const float* __restrict__ x, const float* __restrict__ W,
                                  const float* __restrict__ b, const float* __restrict__ g,
                                  const float* __restrict__ be) {
    int warp = (blockIdx.x * blockDim.x + threadIdx.x) >> 5;
    int lane = threadIdx.x & 31;
    if (warp >= NN) return;
    float x0 = x[warp * 4 + 0], x1 = x[warp * 4 + 1];
    float x2 = x[warp * 4 + 2], x3 = x[warp * 4 + 3];
    int j0 = lane, j1 = lane + 32;
    float y0 = b[j0] + x0 * W[j0] + x1 * W[64 + j0] + x2 * W[128 + j0] + x3 * W[192 + j0];
    float y1 = b[j1] + x0 * W[j1] + x1 * W[64 + j1] + x2 * W[128 + j1] + x3 * W[192 + j1];
    float s = y0 + y1;
    #pragma unroll
    for (int o = 16; o; o >>= 1) s += __shfl_xor_sync(0xffffffffu, s, o);
    float mu = s * (1.0f / 64.0f);
    float d0 = y0 - mu, d1 = y1 - mu;
    float v = d0 * d0 + d1 * d1;
    #pragma unroll
    for (int o = 16; o; o >>= 1) v += __shfl_xor_sync(0xffffffffu, v, o);
    float rs = rsqrtf(v * (1.0f / 64.0f) + 1e-5f);
    g_h[warp * 64 + j0] = fmaxf(d0 * rs * g[j0] + be[j0], 0.0f);
    g_h[warp * 64 + j1] = fmaxf(d1 * rs * g[j1] + be[j1], 0.0f);
}

__global__ void hist_kernel(const int* __restrict__ ei, const int* __restrict__ et) {
    int i = blockIdx.x * blockDim.x + threadIdx.x;
    if (i >= NE) return;
    int dst = ei[NE + i];
    atomicAdd(&g_deg[2 * dst + et[i]], 1);
}

// single-block exclusive scan; 4 elements per thread per iteration
__global__ void scan_kernel() {
    __shared__ int warp_sums[32];
    __shared__ int s_total;
    __shared__ int s_carry;
    int tid = threadIdx.x, lane = tid & 31, wid = tid >> 5;
    if (tid == 0) s_carry = 0;
    __syncthreads();
    for (int base = 0; base < NN; base += 4096) {
        int i0 = base + tid * 4;
        int v[4];
        if (i0 + 3 < NN) {
            int4 a = *reinterpret_cast<const int4*>(&g_deg[2 * i0]);
            int4 b = *reinterpret_cast<const int4*>(&g_deg[2 * i0 + 4]);
            v[0] = a.x + a.y; v[1] = a.z + a.w; v[2] = b.x + b.y; v[3] = b.z + b.w;
        } else {
            #pragma unroll
            for (int j = 0; j < 4; j++) {
                int i = i0 + j;
                v[j] = (i < NN) ? (g_deg[2 * i] + g_deg[2 * i + 1]) : 0;
            }
        }
        int s = v[0] + v[1] + v[2] + v[3];
        int incl = s;
        #pragma unroll
        for (int off = 1; off < 32; off <<= 1) {
            int t = __shfl_up_sync(0xffffffffu, incl, off);
            if (lane >= off) incl += t;
        }
        if (lane == 31) warp_sums[wid] = incl;
        __syncthreads();
        if (wid == 0) {
            int w = warp_sums[lane];
            int wi = w;
            #pragma unroll
            for (int off = 1; off < 32; off <<= 1) {
                int t = __shfl_up_sync(0xffffffffu, wi, off);
                if (lane >= off) wi += t;
            }
            warp_sums[lane] = wi - w;
            if (lane == 31) s_total = wi;
        }
        __syncthreads();
        int run = incl - s + warp_sums[wid] + s_carry;
        #pragma unroll
        for (int j = 0; j < 4; j++) {
            int i = i0 + j;
            if (i < NN) { g_rowoff[i] = run; g_cursor[i] = run; }
            run += v[j];
        }
        __syncthreads();
        if (tid == 0) s_carry += s_total;
        __syncthreads();
    }
    if (threadIdx.x == 0) g_rowoff[NN] = s_carry;
}

__global__ void scatter_kernel(const int* __restrict__ ei, const int* __restrict__ et) {
    int i = blockIdx.x * blockDim.x + threadIdx.x;
    if (i >= NE) return;
    int dst = ei[NE + i];
    int src = ei[i];
    int pos = atomicAdd(&g_cursor[dst], 1);
    g_edge[pos] = src | (et[i] << 30);
}

// ---------------- PQ GEMM: PQ[N x 256] = h[N x 64] @ W1cat[64 x 256], bf16 out ----------------
// 64 rows/block, 256 threads; 64 col-threads x 4 cols, 4 row-threads x 16 rows.
// f32x2 packed FMA over row pairs (smem stride 66 keeps LDS.64 aligned).
__global__ __launch_bounds__(256) void pq_gemm_kernel(const float* __restrict__ A,
                                                      const float* __restrict__ B) {
    __shared__ __align__(16) float Ash[64 * 66];
    const int tid = threadIdx.x;
    const int row0 = blockIdx.x * 64;
    for (int i = tid; i < 64 * 64; i += 256) {
        int r = i >> 6, k = i & 63;
        int gr = row0 + r;
        Ash[k * 66 + r] = (gr < NN) ? A[gr * 64 + k] : 0.0f;
    }
    __syncthreads();
    const int colt = tid & 63;
    const int rowt = tid >> 6;
    const int c0 = colt * 4;
    const int r0 = rowt * 16;
    ull acc[8][4];
    #pragma unroll
    for (int p = 0; p < 8; p++)
        #pragma unroll
        for (int c = 0; c < 4; c++) acc[p][c] = 0ull;
    #pragma unroll 4
    for (int k = 0; k < 64; k++) {
        float4 b4 = *reinterpret_cast<const float4*>(&B[k * 256 + c0]);
        ull bb0 = pack2(b4.x, b4.x), bb1 = pack2(b4.y, b4.y);
        ull bb2 = pack2(b4.z, b4.z), bb3 = pack2(b4.w, b4.w);
        #pragma unroll
        for (int p = 0; p < 8; p++) {
            ull ap = *reinterpret_cast<const ull*>(&Ash[k * 66 + r0 + 2 * p]);
            fma2(acc[p][0], ap, bb0);
            fma2(acc[p][1], ap, bb1);
            fma2(acc[p][2], ap, bb2);
            fma2(acc[p][3], ap, bb3);
        }
    }
    #pragma unroll
    for (int p = 0; p < 8; p++) {
        int gr = row0 + r0 + 2 * p;
        if (gr < NN) {
            float l0, h0, l1, h1, l2, h2, l3, h3;
            unpack2(acc[p][0], l0, h0);
            unpack2(acc[p][1], l1, h1);
            unpack2(acc[p][2], l2, h2);
            unpack2(acc[p][3], l3, h3);
            uint2 pk0, pk1;
            __nv_bfloat162 a0 = __floats2bfloat162_rn(l0, l1);
            __nv_bfloat162 a1 = __floats2bfloat162_rn(l2, l3);
            pk0.x = *reinterpret_cast<unsigned*>(&a0);
            pk0.y = *reinterpret_cast<unsigned*>(&a1);
            *reinterpret_cast<uint2*>(&g_PQ[gr * 256 + c0]) = pk0;
            __nv_bfloat162 b0 = __floats2bfloat162_rn(h0, h1);
            __nv_bfloat162 b1 = __floats2bfloat162_rn(h2, h3);
            pk1.x = *reinterpret_cast<unsigned*>(&b0);
            pk1.y = *reinterpret_cast<unsigned*>(&b1);
            *reinterpret_cast<uint2*>(&g_PQ[(gr + 1) * 256 + c0]) = pk1;
        }
    }
}

// ---------------- fused edge aggregation + W2 GEMV ----------------
// Warp per dst node; lane holds feature pair (2*lane, 2*lane+1). One 128B bf16
// gather per edge, 4x unrolled for MLP. GEMV epilogue in packed f32x2 against
// pre-paired smem W2 (float2 of output cols lane/lane+32 per k).
__global__ __launch_bounds__(256) void agg_kernel(const float* __restrict__ b1,
                                                  const float* __restrict__ b2,
                                                  const float* __restrict__ W2) {
    __shared__ __align__(16) float2 sW2[128 * 32];   // [k][lane] = (W2[k][lane], W2[k][lane+32])
    __shared__ float  sB2[128];
    int tid = threadIdx.x;
    for (int i = tid; i < 128 * 32; i += 256) {
        int k = i >> 5, lane = i & 31;
        sW2[i] = make_float2(W2[k * 64 + lane], W2[k * 64 + 32 + lane]);
    }
    if (tid < 128) sB2[tid] = b2[tid];
    __syncthreads();

    int node = blockIdx.x * 8 + (tid >> 5);
    int lane = tid & 31;
    if (node >= NN) return;
    const __nv_bfloat162* pq2 = reinterpret_cast<const __nv_bfloat162*>(g_PQ);
    float2 q0 = __bfloat1622float2(pq2[node * 128 + 32 + lane]);
    float2 q1 = __bfloat1622float2(pq2[node * 128 + 96 + lane]);
    float b0x = b1[2 * lane], b0y = b1[2 * lane + 1];
    float b1x = b1[64 + 2 * lane], b1y = b1[64 + 2 * lane + 1];
    float a0x = 0.f, a0y = 0.f, a1x = 0.f, a1y = 0.f;
    int c0cnt = 0;
    int beg = g_rowoff[node], end = g_rowoff[node + 1];
    int i = beg;
    for (; i + 3 < end; i += 4) {
        int p0 = __ldg(&g_edge[i]);
        int p1 = __ldg(&g_edge[i + 1]);
        int p2 = __ldg(&g_edge[i + 2]);
        int p3 = __ldg(&g_edge[i + 3]);
        float2 v0 = __bfloat1622float2(__ldg(&pq2[(p0 & 0x3FFFFFFF) * 128 + (((unsigned)p0) >> 30) * 64 + lane]));
        float2 v1 = __bfloat1622float2(__ldg(&pq2[(p1 & 0x3FFFFFFF) * 128 + (((unsigned)p1) >> 30) * 64 + lane]));
        float2 v2 = __bfloat1622float2(__ldg(&pq2[(p2 & 0x3FFFFFFF) * 128 + (((unsigned)p2) >> 30) * 64 + lane]));
        float2 v3 = __bfloat1622float2(__ldg(&pq2[(p3 & 0x3FFFFFFF) * 128 + (((unsigned)p3) >> 30) * 64 + lane]));
        if (p0 >= 0x40000000) { a1x += fmaxf(v0.x + q1.x + b1x, 0.f); a1y += fmaxf(v0.y + q1.y + b1y, 0.f); }
        else { a0x += fmaxf(v0.x + q0.x + b0x, 0.f); a0y += fmaxf(v0.y + q0.y + b0y, 0.f); c0cnt++; }
        if (p1 >= 0x40000000) { a1x += fmaxf(v1.x + q1.x + b1x, 0.f); a1y += fmaxf(v1.y + q1.y + b1y, 0.f); }
        else { a0x += fmaxf(v1.x + q0.x + b0x, 0.f); a0y += fmaxf(v1.y + q0.y + b0y, 0.f); c0cnt++; }
        if (p2 >= 0x40000000) { a1x += fmaxf(v2.x + q1.x + b1x, 0.f); a1y += fmaxf(v2.y + q1.y + b1y, 0.f); }
        else { a0x += fmaxf(v2.x + q0.x + b0x, 0.f); a0y += fmaxf(v2.y + q0.y + b0y, 0.f); c0cnt++; }
        if (p3 >= 0x40000000) { a1x += fmaxf(v3.x + q1.x + b1x, 0.f); a1y += fmaxf(v3.y + q1.y + b1y, 0.f); }
        else { a0x += fmaxf(v3.x + q0.x + b0x, 0.f); a0y += fmaxf(v3.y + q0.y + b0y, 0.f); c0cnt++; }
    }
    for (; i < end; i++) {
        int p = __ldg(&g_edge[i]);
        float2 v = __bfloat1622float2(__ldg(&pq2[(p & 0x3FFFFFFF) * 128 + (((unsigned)p) >> 30) * 64 + lane]));
        if (p >= 0x40000000) { a1x += fmaxf(v.x + q1.x + b1x, 0.f); a1y += fmaxf(v.y + q1.y + b1y, 0.f); }
        else { a0x += fmaxf(v.x + q0.x + b0x, 0.f); a0y += fmaxf(v.y + q0.y + b0y, 0.f); c0cnt++; }
    }
    float c1cnt = (float)((end - beg) - c0cnt);
    // GEMV: op = (o0,o1); k index = feature row of W2cat
    ull op = pack2((float)c0cnt * sB2[lane] + c1cnt * sB2[64 + lane],
                   (float)c0cnt * sB2[32 + lane] + c1cnt * sB2[96 + lane]);
    #pragma unroll
    for (int t = 0; t < 32; t++) {
        float vx = __shfl_sync(0xffffffffu, a0x, t);
        float vy = __shfl_sync(0xffffffffu, a0y, t);
        fma2(op, pack2(vx, vx), *reinterpret_cast<const ull*>(&sW2[(2 * t) * 32 + lane]));
        fma2(op, pack2(vy, vy), *reinterpret_cast<const ull*>(&sW2[(2 * t + 1) * 32 + lane]));
    }
    #pragma unroll
    for (int t = 0; t < 32; t++) {
        float vx = __shfl_sync(0xffffffffu, a1x, t);
        float vy = __shfl_sync(0xffffffffu, a1y, t);
        fma2(op, pack2(vx, vx), *reinterpret_cast<const ull*>(&sW2[(64 + 2 * t) * 32 + lane]));
        fma2(op, pack2(vy, vy), *reinterpret_cast<const ull*>(&sW2[(64 + 2 * t + 1) * 32 + lane]));
    }
    float o0, o1;
    unpack2(op, o0, o1);
    g_agg[node * 64 + lane] = o0;
    g_agg[node * 64 + 32 + lane] = o1;
}

// ---------------- fused GRU: gi = agg@Wi, gh = h@Wh, gates, h update ----------------
// 64 rows/block, 512 threads; f32x2 packed over row pairs (stride 66).
__global__ __launch_bounds__(512) void gru_kernel(const float* __restrict__ Wi,
                                                  const float* __restrict__ Wh,
                                                  const float* __restrict__ bi,
                                                  const float* __restrict__ bh) {
    __shared__ __align__(16) float Aagg[64 * 66];
    __shared__ __align__(16) float Ahh[64 * 66];
    int tid = threadIdx.x;
    int row0 = blockIdx.x * 64;
    for (int i = tid; i < 64 * 64; i += 512) {
        int r = i >> 6, k = i & 63;
        int gr = row0 + r;
        float va = 0.f, vh = 0.f;
        if (gr < NN) { va = g_agg[gr * 64 + k]; vh = g_h[gr * 64 + k]; }
        Aagg[k * 66 + r] = va;
        Ahh[k * 66 + r] = vh;
    }
    __syncthreads();
    int j = tid & 63;
    int rowt = tid >> 6;  // 0..7, 8 rows each -> 4 row pairs
    int r0 = rowt * 8;
    ull ai[4][3], ah[4][3];
    #pragma unroll
    for (int p = 0; p < 4; p++)
        #pragma unroll
        for (int c = 0; c < 3; c++) { ai[p][c] = 0ull; ah[p][c] = 0ull; }

    #pragma unroll 4
    for (int k = 0; k < 64; k++) {
        float wi0 = __ldg(&Wi[k * 192 + j]);
        float wi1 = __ldg(&Wi[k * 192 + 64 + j]);
        float wi2 = __ldg(&Wi[k * 192 + 128 + j]);
        float wh0 = __ldg(&Wh[k * 192 + j]);
        float wh1 = __ldg(&Wh[k * 192 + 64 + j]);
        float wh2 = __ldg(&Wh[k * 192 + 128 + j]);
        ull wwi0 = pack2(wi0, wi0), wwi1 = pack2(wi1, wi1), wwi2 = pack2(wi2, wi2);
        ull wwh0 = pack2(wh0, wh0), wwh1 = pack2(wh1, wh1), wwh2 = pack2(wh2, wh2);
        #pragma unroll
        for (int p = 0; p < 4; p++) {
            ull ap = *reinterpret_cast<const ull*>(&Aagg[k * 66 + r0 + 2 * p]);
            ull hp = *reinterpret_cast<const ull*>(&Ahh[k * 66 + r0 + 2 * p]);
            fma2(ai[p][0], ap, wwi0);
            fma2(ai[p][1], ap, wwi1);
            fma2(ai[p][2], ap, wwi2);
            fma2(ah[p][0], hp, wwh0);
            fma2(ah[p][1], hp, wwh1);
            fma2(ah[p][2], hp, wwh2);
        }
    }
    float bir = bi[j], biz = bi[64 + j], bin = bi[128 + j];
    float bhr = bh[j], bhz = bh[64 + j], bhn = bh[128 + j];
    #pragma unroll
    for (int p = 0; p < 4; p++) {
        float i0r, i1r, i0z, i1z, i0n, i1n;
        float h0r, h1r, h0z, h1z, h0n, h1n;
        unpack2(ai[p][0], i0r, i1r); unpack2(ai[p][1], i0z, i1z); unpack2(ai[p][2], i0n, i1n);
        unpack2(ah[p][0], h0r, h1r); unpack2(ah[p][1], h0z, h1z); unpack2(ah[p][2], h0n, h1n);
        #pragma unroll
        for (int s = 0; s < 2; s++) {
            int rl = r0 + 2 * p + s;
            int gr = row0 + rl;
            if (gr < NN) {
                float irv = s ? i1r : i0r, izv = s ? i1z : i0z, inv = s ? i1n : i0n;
                float hrv = s ? h1r : h0r, hzv = s ? h1z : h0z, hnv = s ? h1n : h0n;
                float rg = 1.0f / (1.0f + expf(-((irv + bir) + (hrv + bhr))));
                float zg = 1.0f / (1.0f + expf(-((izv + biz) + (hzv + bhz))));
                float ng = tanhf((inv + bin) + rg * (hnv + bhn));
                float hold = Ahh[j * 66 + rl];
                g_h[gr * 64 + j] = (1.0f - zg) * ng + zg * hold;
            }
        }
    }
}

// ---------------- readout + final correction; warp per node ----------------
__global__ void readout_kernel(const float* __restrict__ w1, const float* __restrict__ b1,
                               const float* __restrict__ w2, const float* __restrict__ b2,
                               const int* __restrict__ ntype, const float* __restrict__ x,
                               float* __restrict__ out) {
    int node = (blockIdx.x * blockDim.x + threadIdx.x) >> 5;
    int lane = threadIdx.x & 31;
    if (node >= NN) return;
    float h0 = g_h[node * 64 + lane];
    float h1 = g_h[node * 64 + 32 + lane];
    float a0 = b1[lane], a1 = b1[32 + lane];
    #pragma unroll
    for (int k = 0; k < 32; k++) {
        float hk = __shfl_sync(0xffffffffu, h0, k);
        a0 = fmaf(hk, w1[k * 64 + lane], a0);
        a1 = fmaf(hk, w1[k * 64 + 32 + lane], a1);
    }
    #pragma unroll
    for (int k = 0; k < 32; k++) {
        float hk = __shfl_sync(0xffffffffu, h1, k);
        a0 = fmaf(hk, w1[(32 + k) * 64 + lane], a0);
        a1 = fmaf(hk, w1[(32 + k) * 64 + 32 + lane], a1);
    }
    a0 = fmaxf(a0, 0.0f);
    a1 = fmaxf(a1, 0.0f);
    float s = a0 * w2[lane] + a1 * w2[32 + lane];
    #pragma unroll
    for (int o = 16; o; o >>= 1) s += __shfl_xor_sync(0xffffffffu, s, o);
    if (lane == 0) {
        float o_ = s + b2[0];
        out[node] = (ntype[node] == 0) ? (x[node * 4] + o_) : 0.0f;
    }
}

// ---------------- launcher ----------------
extern "C" void kernel_launch(void* const* d_in, const int* in_sizes, int n_in,
                              void* d_out, int out_size) {
    const float* x          = (const float*)d_in[0];
    const int*   node_type  = (const int*)d_in[1];
    const int*   edge_index = (const int*)d_in[2];
    const int*   edge_type  = (const int*)d_in[3];
    const float* in_w       = (const float*)d_in[4];
    const float* in_b       = (const float*)d_in[5];
    const float* ln_g       = (const float*)d_in[6];
    const float* ln_b       = (const float*)d_in[7];
    const float* mlp_w1     = (const float*)d_in[8];
    const float* mlp_b1     = (const float*)d_in[9];
    const float* mlp_w2     = (const float*)d_in[10];
    const float* mlp_b2     = (const float*)d_in[11];
    const float* gru_wi     = (const float*)d_in[12];
    const float* gru_wh     = (const float*)d_in[13];
    const float* gru_bi     = (const float*)d_in[14];
    const float* gru_bh     = (const float*)d_in[15];
    const float* ro_w1      = (const float*)d_in[16];
    const float* ro_b1      = (const float*)d_in[17];
    const float* ro_w2      = (const float*)d_in[18];
    const float* ro_b2      = (const float*)d_in[19];
    float* out = (float*)d_out;

    float *p_h, *p_W1, *p_W2;
    cudaGetSymbolAddress((void**)&p_h, g_h);
    cudaGetSymbolAddress((void**)&p_W1, g_W1cat);
    cudaGetSymbolAddress((void**)&p_W2, g_W2cat);

    const int nwarp_blocks = (NN + 7) / 8;
    const int gemm_blocks  = (NN + 63) / 64;
    const int edge_blocks  = (NE + 255) / 256;

    zero_deg_kernel<<<(2 * NN + 255) / 256, 256>>>();
    pack_kernel<<<(NL * 64 * 256 + NL * 128 * 64 + 255) / 256, 256>>>(mlp_w1, mlp_w2);
    input_proj_kernel<<<nwarp_blocks, 256>>>(x, in_w, in_b, ln_g, ln_b);
    hist_kernel<<<edge_blocks, 256>>>(edge_index, edge_type);
    scan_kernel<<<1, 1024>>>();
    scatter_kernel<<<edge_blocks, 256>>>(edge_index, edge_type);

    for (int l = 0; l < NL; l++) {
        pq_gemm_kernel<<<gemm_blocks, 256>>>(p_h, p_W1 + l * 64 * 256);
        agg_kernel<<<nwarp_blocks, 256>>>(mlp_b1 + l * 2 * 64, mlp_b2 + l * 2 * 64,
                                          p_W2 + l * 128 * 64);
        gru_kernel<<<gemm_blocks, 512>>>(gru_wi + l * 64 * 192, gru_wh + l * 64 * 192,
                                         gru_bi + l * 192, gru_bh + l * 192);
    }

    readout_kernel<<<nwarp_blocks, 256>>>(ro_w1, ro_b1, ro_w2, ro_b2, node_type, x, out);
}